// round 9
// baseline (speedup 1.0000x reference)
#include <cuda_runtime.h>
#include <cuda_fp16.h>
#include <cstdint>
#include <math.h>

// ---------------- Problem constants ----------------
#define BATCH 8
#define SEQ   2048
#define HID   512
#define NHEAD 8
#define DHEAD 64
#define MROWS (BATCH*SEQ)          // 16384
#define FFN   (4*HID)              // 2048
#define BHSD  ((size_t)BATCH*NHEAD*SEQ*DHEAD)

// ---------------- Scratch (device globals) ----------------
__device__ __half g_QKVh[3 * BHSD];                    // Q|K|V in [b,h,s,d] fp16
__device__ __half g_AttnH[(size_t)MROWS*HID];          // attention out, fp16 row-major
__device__ float  g_R [(size_t)MROWS*HID];             // residual sums (fp32)
__device__ float  g_L1[(size_t)MROWS*HID];             // LN1 out (fp32)
__device__ __half g_Xh[(size_t)MROWS*HID];             // X fp16 (QKV input)
__device__ __half g_L1h[(size_t)MROWS*HID];            // LN1 out fp16 (FFN1 input)
__device__ __half g_F2[(size_t)MROWS*FFN];             // FFN hidden fp16
__device__ __half g_Wqkv[(size_t)3*HID*HID];           // [1536][512]
__device__ __half g_Woh [(size_t)HID*HID];             // [512][512]
__device__ __half g_W1h [(size_t)FFN*HID];             // [2048][512]
__device__ __half g_W2h [(size_t)HID*FFN];             // [512][2048]
__device__ float  g_bqkv[3*HID];

// ---------------- PTX helpers ----------------
__device__ __forceinline__ uint32_t smem_u32(const void* p) {
    uint32_t a;
    asm("{ .reg .u64 t; cvta.to.shared.u64 t, %1; cvt.u32.u64 %0, t; }" : "=r"(a) : "l"(p));
    return a;
}
#define CP16(s, g)   asm volatile("cp.async.cg.shared.global [%0], [%1], 16;" :: "r"(s), "l"(g))
#define CP_COMMIT()  asm volatile("cp.async.commit_group;" ::: "memory")
#define CP_WAIT(n)   asm volatile("cp.async.wait_group %0;" :: "n"(n) : "memory")

__device__ __forceinline__ void ldm_x4(uint32_t* r, uint32_t a) {
    asm volatile("ldmatrix.sync.aligned.m8n8.x4.shared.b16 {%0,%1,%2,%3}, [%4];"
                 : "=r"(r[0]), "=r"(r[1]), "=r"(r[2]), "=r"(r[3]) : "r"(a));
}
__device__ __forceinline__ void ldm_x4_t(uint32_t* r, uint32_t a) {
    asm volatile("ldmatrix.sync.aligned.m8n8.x4.trans.shared.b16 {%0,%1,%2,%3}, [%4];"
                 : "=r"(r[0]), "=r"(r[1]), "=r"(r[2]), "=r"(r[3]) : "r"(a));
}
__device__ __forceinline__ void mma_f16(float* c, const uint32_t* a, uint32_t b0, uint32_t b1) {
    asm volatile("mma.sync.aligned.m16n8k16.row.col.f32.f16.f16.f32 "
                 "{%0,%1,%2,%3}, {%4,%5,%6,%7}, {%8,%9}, {%0,%1,%2,%3};"
                 : "+f"(c[0]), "+f"(c[1]), "+f"(c[2]), "+f"(c[3])
                 : "r"(a[0]), "r"(a[1]), "r"(a[2]), "r"(a[3]), "r"(b0), "r"(b1));
}
__device__ __forceinline__ uint32_t pack_h(float lo, float hi) {
    uint32_t r;
    asm("cvt.rn.f16x2.f32 %0, %1, %2;" : "=r"(r) : "f"(hi), "f"(lo));
    return r;
}
__device__ __forceinline__ float ex2f(float x) {
    float r;
    asm("ex2.approx.f32 %0, %1;" : "=f"(r) : "f"(x));
    return r;
}

// 128B-row swizzle (64 fp16 per row): row r, 16B chunk q
__device__ __forceinline__ uint32_t off128(int r, int q) {
    return ((uint32_t)r << 7) + ((uint32_t)((q ^ (r & 7))) << 4);
}

// =====================================================================
// Conversion kernels
// =====================================================================
__global__ __launch_bounds__(256)
void convert_x(const float* __restrict__ in, __half* __restrict__ out, int total)
{
    int idx = blockIdx.x * 256 + threadIdx.x;
    if (idx < total) out[idx] = __float2half_rn(in[idx]);
}

__global__ __launch_bounds__(256)
void convert_wt1(const float* __restrict__ W, __half* __restrict__ Bt, int K, int N)
{
    int idx = blockIdx.x * 256 + threadIdx.x;
    if (idx >= K * N) return;
    int n = idx / K, k = idx % K;
    Bt[(size_t)n * K + k] = __float2half_rn(W[(size_t)k * N + n]);
}

__global__ __launch_bounds__(256)
void convert_wt4(const float* __restrict__ W0, const float* __restrict__ W1,
                 const float* __restrict__ W2, const float* __restrict__ W3,
                 __half* __restrict__ O0, __half* __restrict__ O1,
                 __half* __restrict__ O2, __half* __restrict__ O3)
{
    int gid = blockIdx.x * 256 + threadIdx.x;
    int which = gid >> 18;
    int idx = gid & ((1 << 18) - 1);
    int n = idx >> 9, k = idx & 511;
    const float* W = (which == 0) ? W0 : (which == 1) ? W1 : (which == 2) ? W2 : W3;
    __half* O = (which == 0) ? O0 : (which == 1) ? O1 : (which == 2) ? O2 : O3;
    O[(size_t)n * HID + k] = __float2half_rn(W[(size_t)k * HID + n]);
}

__global__ void bias_cat(const float* bq, const float* bk, const float* bv, float* o)
{
    int i = blockIdx.x * 256 + threadIdx.x;
    if (i < HID) { o[i] = bq[i]; o[HID + i] = bk[i]; o[2 * HID + i] = bv[i]; }
}

// =====================================================================
// fp16 mma.sync GEMM v4: BM=128, BN=256, BK=64; 8 warps (2x4), 64x64
// warp tiles; 256 threads, 1 CTA/SM, 4-stage cp.async (48KB/stage).
// MODE 2: fp32 out = acc + bias + res
// MODE 3: QKV: fp16 out to head layout with per-col alpha (Q only)
// MODE 4: relu, fp16 out (FFN1)
// =====================================================================
#define STG_SZ 49152     // 16KB A + 32KB B

template<int MODE>
__global__ __launch_bounds__(256, 1)
void mm_gemm(const __half* __restrict__ A, const __half* __restrict__ Bt,
             const float* __restrict__ bias, const float* __restrict__ res,
             float* __restrict__ C, __half* __restrict__ Ch,
             int N, int Kstride, int Kiter, float alpha)
{
    extern __shared__ char smc[];
    const uint32_t sb = smem_u32(smc);
    const int tid = threadIdx.x, lane = tid & 31, w = tid >> 5;
    const int wm = w >> 2, wn = w & 3;                 // 2 x 4 warp grid
    const int bm = blockIdx.y * 128, bn = blockIdx.x * 256;
    const int nt = Kiter / 64;
    const __half* Ag = A + (size_t)bm * Kstride;
    const __half* Bg = Bt + (size_t)bn * Kstride;

    auto load_tile = [&](int t) {
        const int st = t & 3;
        const uint32_t sa = sb + st * STG_SZ, sbb = sa + 16384;
        const __half* Ap = Ag + t * 64;
        const __half* Bp = Bg + t * 64;
        // A: 128 rows x 8 chunks = 1024 CP16 (4/thread)
        #pragma unroll
        for (int i = 0; i < 4; i++) {
            int idx = tid + i * 256;
            int r = idx >> 3, q = idx & 7;
            CP16(sa + off128(r, q), Ap + (size_t)r * Kstride + q * 8);
        }
        // B: 256 rows x 8 chunks = 2048 CP16 (8/thread)
        #pragma unroll
        for (int i = 0; i < 8; i++) {
            int idx = tid + i * 256;
            int r = idx >> 3, q = idx & 7;
            CP16(sbb + off128(r, q), Bp + (size_t)r * Kstride + q * 8);
        }
        CP_COMMIT();
    };
    load_tile(0); load_tile(1); load_tile(2);

    float acc[4][8][4];
    #pragma unroll
    for (int a0 = 0; a0 < 4; a0++)
        #pragma unroll
        for (int b0 = 0; b0 < 8; b0++)
            #pragma unroll
            for (int c0 = 0; c0 < 4; c0++) acc[a0][b0][c0] = 0.f;

    for (int t = 0; t < nt; t++) {
        CP_WAIT(2);
        __syncthreads();
        if (t + 3 < nt) load_tile(t + 3);
        const int st = t & 3;
        const uint32_t sa = sb + st * STG_SZ, sbb = sa + 16384;
        #pragma unroll
        for (int j = 0; j < 4; j++) {
            uint32_t af[4][4], bf[4][4];
            const int q = j * 2 + (lane >> 4);
            #pragma unroll
            for (int mi = 0; mi < 4; mi++) {
                int r = wm * 64 + mi * 16 + (lane & 15);
                ldm_x4(af[mi], sa + off128(r, q));
            }
            #pragma unroll
            for (int ni = 0; ni < 4; ni++) {
                int r = wn * 64 + ni * 16 + (lane & 15);
                ldm_x4(bf[ni], sbb + off128(r, q));
            }
            #pragma unroll
            for (int mi = 0; mi < 4; mi++)
                #pragma unroll
                for (int nj = 0; nj < 8; nj++)
                    mma_f16(acc[mi][nj], af[mi],
                            bf[nj >> 1][nj & 1], bf[nj >> 1][2 + (nj & 1)]);
        }
    }

    // epilogue: row = bm + wm*64 + mi*16 + hh*8 + lane/4
    //           col = bn + wn*64 + nj*8 + 2*(lane%4)
    #pragma unroll
    for (int mi = 0; mi < 4; mi++) {
        #pragma unroll
        for (int hh = 0; hh < 2; hh++) {
            const int row = bm + wm * 64 + mi * 16 + hh * 8 + (lane >> 2);
            #pragma unroll
            for (int nj = 0; nj < 8; nj++) {
                const int col = bn + wn * 64 + nj * 8 + 2 * (lane & 3);
                float v0 = acc[mi][nj][2 * hh]     + bias[col];
                float v1 = acc[mi][nj][2 * hh + 1] + bias[col + 1];
                if (MODE == 2) {
                    float2 rr = *(const float2*)(res + (size_t)row * N + col);
                    float2 vv; vv.x = v0 + rr.x; vv.y = v1 + rr.y;
                    *(float2*)(C + (size_t)row * N + col) = vv;
                }
                if (MODE == 3) {
                    float sc = (col < HID) ? alpha : 1.f;
                    int t = col >> 9, rem = col & 511;
                    int b = row >> 11, s = row & 2047, hd = rem >> 6, d = rem & 63;
                    __half2 p;
                    p.x = __float2half_rn(v0 * sc);
                    p.y = __float2half_rn(v1 * sc);
                    *(__half2*)(g_QKVh + (size_t)t * BHSD +
                        ((((size_t)b * NHEAD + hd) * SEQ + s) * DHEAD + d)) = p;
                }
                if (MODE == 4) {
                    __half2 p;
                    p.x = __float2half_rn(fmaxf(v0, 0.f));
                    p.y = __float2half_rn(fmaxf(v1, 0.f));
                    *(__half2*)(Ch + (size_t)row * N + col) = p;
                }
            }
        }
    }
}

// =====================================================================
// FA2-style fp16 attention, no online max, exp2 softmax.
// 128 q/CTA, 4 warps. 4-stage KV ring, 2 chunks per loop body.
// smem: Q 16KB + 4 x (K 8KB + V 8KB) = 80KB.
// =====================================================================
__global__ __launch_bounds__(128)
void attn_mma(__half* __restrict__ AoutH)
{
    extern __shared__ char smc[];
    const uint32_t sb = smem_u32(smc);
    const int tid = threadIdx.x, lane = tid & 31, w = tid >> 5;
    const int bh = blockIdx.y, qbase = blockIdx.x * 128;
    const int b = bh >> 3, h = bh & 7;
    const __half* Qp = g_QKVh + ((size_t)bh * SEQ + qbase) * DHEAD;
    const __half* Kp = g_QKVh + BHSD + (size_t)bh * SEQ * DHEAD;
    const __half* Vp = g_QKVh + 2 * BHSD + (size_t)bh * SEQ * DHEAD;

    #pragma unroll
    for (int i = 0; i < 8; i++) {
        int idx = tid + i * 128;
        int r = idx >> 3, q = idx & 7;
        *(uint4*)(smc + off128(r, q)) = *(const uint4*)(Qp + (size_t)r * DHEAD + q * 8);
    }
    __syncthreads();

    uint32_t qf[2][4][4];
    #pragma unroll
    for (int mi = 0; mi < 2; mi++)
        #pragma unroll
        for (int dk = 0; dk < 4; dk++) {
            int r = w * 32 + mi * 16 + (lane & 15);
            int q = dk * 2 + (lane >> 4);
            ldm_x4(qf[mi][dk], sb + off128(r, q));
        }

    float o[2][8][4];
    #pragma unroll
    for (int mi = 0; mi < 2; mi++)
        #pragma unroll
        for (int dj = 0; dj < 8; dj++)
            #pragma unroll
            for (int c0 = 0; c0 < 4; c0++) o[mi][dj][c0] = 0.f;
    float lrun[2][2] = {{0.f, 0.f}, {0.f, 0.f}};

    auto load_kv = [&](int c) {
        const int st = c & 3;
        const uint32_t sk = sb + 16384 + st * 16384;
        const uint32_t sv = sk + 8192;
        const __half* Kc = Kp + (size_t)c * 64 * DHEAD;
        const __half* Vc = Vp + (size_t)c * 64 * DHEAD;
        #pragma unroll
        for (int i = 0; i < 4; i++) {
            int idx = tid + i * 128;
            int r = idx >> 3, q = idx & 7;
            uint32_t so = off128(r, q);
            CP16(sk + so, Kc + (size_t)r * DHEAD + q * 8);
            CP16(sv + so, Vc + (size_t)r * DHEAD + q * 8);
        }
        CP_COMMIT();
    };

    auto compute_chunk = [&](int c) {
        const int st = c & 3;
        const uint32_t sk = sb + 16384 + st * 16384;
        const uint32_t sv = sk + 8192;

        float s[2][8][4];
        #pragma unroll
        for (int mi = 0; mi < 2; mi++)
            #pragma unroll
            for (int nj = 0; nj < 8; nj++)
                #pragma unroll
                for (int c0 = 0; c0 < 4; c0++) s[mi][nj][c0] = 0.f;

        #pragma unroll
        for (int dk = 0; dk < 4; dk++) {
            uint32_t kf[4][4];
            const int q = dk * 2 + (lane >> 4);
            #pragma unroll
            for (int bq = 0; bq < 4; bq++) {
                int r = bq * 16 + (lane & 15);
                ldm_x4(kf[bq], sk + off128(r, q));
            }
            #pragma unroll
            for (int mi = 0; mi < 2; mi++)
                #pragma unroll
                for (int nj = 0; nj < 8; nj++)
                    mma_f16(s[mi][nj], qf[mi][dk],
                            kf[nj >> 1][nj & 1], kf[nj >> 1][2 + (nj & 1)]);
        }

        // P = 2^S (log2e folded into Q scale)
        #pragma unroll
        for (int mi = 0; mi < 2; mi++)
            #pragma unroll
            for (int hh = 0; hh < 2; hh++) {
                float sum = 0.f;
                #pragma unroll
                for (int nj = 0; nj < 8; nj++) {
                    float e0 = ex2f(s[mi][nj][2 * hh]);
                    float e1 = ex2f(s[mi][nj][2 * hh + 1]);
                    s[mi][nj][2 * hh] = e0;
                    s[mi][nj][2 * hh + 1] = e1;
                    sum += e0 + e1;
                }
                lrun[mi][hh] += sum;
            }

        uint32_t pf[2][4][4];
        #pragma unroll
        for (int mi = 0; mi < 2; mi++)
            #pragma unroll
            for (int ki = 0; ki < 4; ki++) {
                pf[mi][ki][0] = pack_h(s[mi][2 * ki][0],     s[mi][2 * ki][1]);
                pf[mi][ki][1] = pack_h(s[mi][2 * ki][2],     s[mi][2 * ki][3]);
                pf[mi][ki][2] = pack_h(s[mi][2 * ki + 1][0], s[mi][2 * ki + 1][1]);
                pf[mi][ki][3] = pack_h(s[mi][2 * ki + 1][2], s[mi][2 * ki + 1][3]);
            }

        #pragma unroll
        for (int ki = 0; ki < 4; ki++) {
            uint32_t vf[4][4];
            #pragma unroll
            for (int db = 0; db < 4; db++) {
                int r = ki * 16 + (lane & 15);
                int q = db * 2 + (lane >> 4);
                ldm_x4_t(vf[db], sv + off128(r, q));
            }
            #pragma unroll
            for (int mi = 0; mi < 2; mi++)
                #pragma unroll
                for (int dj = 0; dj < 8; dj++)
                    mma_f16(o[mi][dj], pf[mi][ki],
                            vf[dj >> 1][(dj & 1) * 2], vf[dj >> 1][(dj & 1) * 2 + 1]);
        }
    };

    load_kv(0); load_kv(1); load_kv(2); load_kv(3);

    const int NC = SEQ / 64;
    for (int c = 0; c < NC; c += 2) {
        CP_WAIT(2);
        __syncthreads();
        compute_chunk(c);
        compute_chunk(c + 1);
        __syncthreads();
        if (c + 4 < NC) load_kv(c + 4);
        if (c + 5 < NC) load_kv(c + 5);
    }

    #pragma unroll
    for (int mi = 0; mi < 2; mi++)
        #pragma unroll
        for (int hh = 0; hh < 2; hh++) {
            lrun[mi][hh] += __shfl_xor_sync(0xffffffffu, lrun[mi][hh], 1);
            lrun[mi][hh] += __shfl_xor_sync(0xffffffffu, lrun[mi][hh], 2);
        }

    #pragma unroll
    for (int mi = 0; mi < 2; mi++)
        #pragma unroll
        for (int hh = 0; hh < 2; hh++) {
            const int srow = qbase + w * 32 + mi * 16 + hh * 8 + (lane >> 2);
            const float inv = 1.f / lrun[mi][hh];
            #pragma unroll
            for (int dj = 0; dj < 8; dj++) {
                const int col = h * 64 + dj * 8 + 2 * (lane & 3);
                __half2 p;
                p.x = __float2half_rn(o[mi][dj][2 * hh] * inv);
                p.y = __float2half_rn(o[mi][dj][2 * hh + 1] * inv);
                *(__half2*)(AoutH + ((size_t)b * SEQ + srow) * HID + col) = p;
            }
        }
}

// =====================================================================
// LayerNorm. HOUT=1 also writes plain fp16 row (FFN1 input).
// =====================================================================
template<int HOUT>
__global__ __launch_bounds__(128)
void layernorm_kernel(const float* __restrict__ X, const float* __restrict__ g,
                      const float* __restrict__ b, float* __restrict__ Y,
                      __half* __restrict__ Yh)
{
    const int row = blockIdx.x;
    const int tid = threadIdx.x;
    const float4 v = ((const float4*)(X + (size_t)row * HID))[tid];

    float s  = v.x + v.y + v.z + v.w;
    float ss = v.x*v.x + v.y*v.y + v.z*v.z + v.w*v.w;
    #pragma unroll
    for (int o = 16; o > 0; o >>= 1) {
        s  += __shfl_xor_sync(0xffffffffu, s,  o);
        ss += __shfl_xor_sync(0xffffffffu, ss, o);
    }
    __shared__ float sh[8];
    const int wid = tid >> 5, lane = tid & 31;
    if (lane == 0) { sh[wid] = s; sh[4 + wid] = ss; }
    __syncthreads();
    s  = sh[0] + sh[1] + sh[2] + sh[3];
    ss = sh[4] + sh[5] + sh[6] + sh[7];

    const float mean = s * (1.f / HID);
    const float var  = ss * (1.f / HID) - mean * mean;
    const float rstd = rsqrtf(var + 1e-5f);

    const float4 gg = ((const float4*)g)[tid];
    const float4 bb = ((const float4*)b)[tid];
    float4 out;
    out.x = (v.x - mean) * rstd * gg.x + bb.x;
    out.y = (v.y - mean) * rstd * gg.y + bb.y;
    out.z = (v.z - mean) * rstd * gg.z + bb.z;
    out.w = (v.w - mean) * rstd * gg.w + bb.w;
    ((float4*)(Y + (size_t)row * HID))[tid] = out;

    if (HOUT) {
        __half2 a, c;
        a.x = __float2half_rn(out.x); a.y = __float2half_rn(out.y);
        c.x = __float2half_rn(out.z); c.y = __float2half_rn(out.w);
        *(__half2*)(Yh + (size_t)row * HID + tid * 4) = a;
        *(__half2*)(Yh + (size_t)row * HID + tid * 4 + 2) = c;
    }
}

// =====================================================================
// Launch
// =====================================================================
extern "C" void kernel_launch(void* const* d_in, const int* in_sizes, int n_in,
                              void* d_out, int out_size)
{
    const float* X   = (const float*)d_in[0];
    const float* Wq  = (const float*)d_in[2];
    const float* bq  = (const float*)d_in[3];
    const float* Wk  = (const float*)d_in[4];
    const float* bk  = (const float*)d_in[5];
    const float* Wv  = (const float*)d_in[6];
    const float* bv  = (const float*)d_in[7];
    const float* Wo  = (const float*)d_in[8];
    const float* bo  = (const float*)d_in[9];
    const float* g1  = (const float*)d_in[10];
    const float* b1  = (const float*)d_in[11];
    const float* W1  = (const float*)d_in[12];
    const float* bf1 = (const float*)d_in[13];
    const float* W2  = (const float*)d_in[14];
    const float* bf2 = (const float*)d_in[15];
    const float* g2  = (const float*)d_in[16];
    const float* b2  = (const float*)d_in[17];
    float* out = (float*)d_out;

    void *pQKV,*pAtt,*pR,*pL1,*pXh,*pL1h,*pF2,*pWqkv,*pWoh,*pW1h,*pW2h,*pBqkv;
    cudaGetSymbolAddress(&pQKV, g_QKVh); cudaGetSymbolAddress(&pAtt, g_AttnH);
    cudaGetSymbolAddress(&pR, g_R);      cudaGetSymbolAddress(&pL1, g_L1);
    cudaGetSymbolAddress(&pXh, g_Xh);    cudaGetSymbolAddress(&pL1h, g_L1h);
    cudaGetSymbolAddress(&pF2, g_F2);    cudaGetSymbolAddress(&pWqkv, g_Wqkv);
    cudaGetSymbolAddress(&pWoh, g_Woh);  cudaGetSymbolAddress(&pW1h, g_W1h);
    cudaGetSymbolAddress(&pW2h, g_W2h);  cudaGetSymbolAddress(&pBqkv, g_bqkv);

    const int GEMM_SMEM = 4 * STG_SZ;    // 4 stages x 48KB = 192KB
    cudaFuncSetAttribute(mm_gemm<2>, cudaFuncAttributeMaxDynamicSharedMemorySize, GEMM_SMEM);
    cudaFuncSetAttribute(mm_gemm<3>, cudaFuncAttributeMaxDynamicSharedMemorySize, GEMM_SMEM);
    cudaFuncSetAttribute(mm_gemm<4>, cudaFuncAttributeMaxDynamicSharedMemorySize, GEMM_SMEM);
    const int ATT_SMEM = 81920;          // Q 16KB + 4 x 16KB KV
    cudaFuncSetAttribute(attn_mma, cudaFuncAttributeMaxDynamicSharedMemorySize, ATT_SMEM);

    // log2(e)/sqrt(dh): folds attention scale and exp->exp2 base change into Q
    const float qscale = 1.44269504088896340736f / sqrtf((float)DHEAD);

    // conversions
    bias_cat<<<2, 256>>>(bq, bk, bv, (float*)pBqkv);
    convert_x<<<(MROWS*HID + 255)/256, 256>>>(X, (__half*)pXh, MROWS*HID);
    convert_wt4<<<(4*HID*HID)/256, 256>>>(Wq, Wk, Wv, Wo,
        (__half*)pWqkv, (__half*)pWqkv + (size_t)HID*HID,
        (__half*)pWqkv + (size_t)2*HID*HID, (__half*)pWoh);
    convert_wt1<<<(HID*FFN + 255)/256, 256>>>(W1, (__half*)pW1h, HID, FFN);
    convert_wt1<<<(FFN*HID + 255)/256, 256>>>(W2, (__half*)pW2h, FFN, HID);

    // fused QKV projection -> fp16 head layout
    mm_gemm<3><<<dim3(3*HID/256, MROWS/128), 256, GEMM_SMEM>>>(
        (__half*)pXh, (__half*)pWqkv, (float*)pBqkv, nullptr, nullptr, nullptr,
        3*HID, HID, HID, qscale);

    // attention
    attn_mma<<<dim3(SEQ/128, BATCH*NHEAD), 128, ATT_SMEM>>>((__half*)pAtt);

    // Wo + residual, LN1 (+fp16 out)
    mm_gemm<2><<<dim3(HID/256, MROWS/128), 256, GEMM_SMEM>>>(
        (__half*)pAtt, (__half*)pWoh, bo, X, (float*)pR, nullptr, HID, HID, HID, 1.f);
    layernorm_kernel<1><<<MROWS, 128>>>((float*)pR, g1, b1, (float*)pL1, (__half*)pL1h);

    // FFN1: plain fp16, relu
    mm_gemm<4><<<dim3(FFN/256, MROWS/128), 256, GEMM_SMEM>>>(
        (__half*)pL1h, (__half*)pW1h, bf1, nullptr, nullptr, (__half*)pF2,
        FFN, HID, HID, 1.f);

    // FFN2: plain fp16 + residual
    mm_gemm<2><<<dim3(HID/256, MROWS/128), 256, GEMM_SMEM>>>(
        (__half*)pF2, (__half*)pW2h, bf2, (float*)pL1, (float*)pR, nullptr,
        HID, FFN, FFN, 1.f);

    // LN2 -> out
    layernorm_kernel<0><<<MROWS, 128>>>((float*)pR, g2, b2, out, nullptr);
}

// round 12
// speedup vs baseline: 1.0009x; 1.0009x over previous
#include <cuda_runtime.h>
#include <cuda_fp16.h>
#include <cstdint>
#include <math.h>

// ---------------- Problem constants ----------------
#define BATCH 8
#define SEQ   2048
#define HID   512
#define NHEAD 8
#define DHEAD 64
#define MROWS (BATCH*SEQ)          // 16384
#define FFN   (4*HID)              // 2048
#define BHSD  ((size_t)BATCH*NHEAD*SEQ*DHEAD)

// ---------------- Scratch (device globals) ----------------
__device__ __half g_QKVh[3 * BHSD];                    // Q|K|V in [b,h,s,d] fp16
__device__ __half g_AttnH[(size_t)MROWS*HID];          // attention out, fp16 row-major
__device__ float  g_R [(size_t)MROWS*HID];             // residual sums (fp32)
__device__ float  g_L1[(size_t)MROWS*HID];             // LN1 out (fp32)
__device__ __half g_Xh[(size_t)MROWS*HID];             // X fp16 (QKV input)
__device__ __half g_L1h[(size_t)MROWS*HID];            // LN1 out fp16 (FFN1 input)
__device__ __half g_F2[(size_t)MROWS*FFN];             // FFN hidden fp16
__device__ __half g_Wqkv[(size_t)3*HID*HID];           // [1536][512]
__device__ __half g_Woh [(size_t)HID*HID];             // [512][512]
__device__ __half g_W1h [(size_t)FFN*HID];             // [2048][512]
__device__ __half g_W2h [(size_t)HID*FFN];             // [512][2048]
__device__ float  g_bqkv[3*HID];

// ---------------- PTX helpers ----------------
__device__ __forceinline__ uint32_t smem_u32(const void* p) {
    uint32_t a;
    asm("{ .reg .u64 t; cvta.to.shared.u64 t, %1; cvt.u32.u64 %0, t; }" : "=r"(a) : "l"(p));
    return a;
}
#define CP16(s, g)   asm volatile("cp.async.cg.shared.global [%0], [%1], 16;" :: "r"(s), "l"(g))
#define CP_COMMIT()  asm volatile("cp.async.commit_group;" ::: "memory")
#define CP_WAIT(n)   asm volatile("cp.async.wait_group %0;" :: "n"(n) : "memory")

__device__ __forceinline__ void ldm_x4(uint32_t* r, uint32_t a) {
    asm volatile("ldmatrix.sync.aligned.m8n8.x4.shared.b16 {%0,%1,%2,%3}, [%4];"
                 : "=r"(r[0]), "=r"(r[1]), "=r"(r[2]), "=r"(r[3]) : "r"(a));
}
__device__ __forceinline__ void ldm_x4_t(uint32_t* r, uint32_t a) {
    asm volatile("ldmatrix.sync.aligned.m8n8.x4.trans.shared.b16 {%0,%1,%2,%3}, [%4];"
                 : "=r"(r[0]), "=r"(r[1]), "=r"(r[2]), "=r"(r[3]) : "r"(a));
}
__device__ __forceinline__ void mma_f16(float* c, const uint32_t* a, uint32_t b0, uint32_t b1) {
    asm volatile("mma.sync.aligned.m16n8k16.row.col.f32.f16.f16.f32 "
                 "{%0,%1,%2,%3}, {%4,%5,%6,%7}, {%8,%9}, {%0,%1,%2,%3};"
                 : "+f"(c[0]), "+f"(c[1]), "+f"(c[2]), "+f"(c[3])
                 : "r"(a[0]), "r"(a[1]), "r"(a[2]), "r"(a[3]), "r"(b0), "r"(b1));
}
__device__ __forceinline__ uint32_t pack_h(float lo, float hi) {
    uint32_t r;
    asm("cvt.rn.f16x2.f32 %0, %1, %2;" : "=r"(r) : "f"(hi), "f"(lo));
    return r;
}
__device__ __forceinline__ float ex2f(float x) {
    float r;
    asm("ex2.approx.f32 %0, %1;" : "=f"(r) : "f"(x));
    return r;
}

// 128B-row swizzle (64 fp16 per row): row r, 16B chunk q
__device__ __forceinline__ uint32_t off128(int r, int q) {
    return ((uint32_t)r << 7) + ((uint32_t)((q ^ (r & 7))) << 4);
}

// =====================================================================
// Conversion kernels
// =====================================================================
__global__ __launch_bounds__(256)
void convert_x(const float* __restrict__ in, __half* __restrict__ out, int total)
{
    int idx = blockIdx.x * 256 + threadIdx.x;
    if (idx < total) out[idx] = __float2half_rn(in[idx]);
}

// merged W1 + W2 transpose converts (one launch)
__global__ __launch_bounds__(256)
void convert_w12(const float* __restrict__ W1, const float* __restrict__ W2,
                 __half* __restrict__ O1, __half* __restrict__ O2)
{
    int gid = blockIdx.x * 256 + threadIdx.x;
    const int half1 = HID * FFN;
    if (gid < half1) {
        int n = gid / HID, k = gid % HID;          // O1: [FFN][HID]
        O1[(size_t)n * HID + k] = __float2half_rn(W1[(size_t)k * FFN + n]);
    } else {
        int idx = gid - half1;
        int n = idx / FFN, k = idx % FFN;          // O2: [HID][FFN]
        O2[(size_t)n * FFN + k] = __float2half_rn(W2[(size_t)k * HID + n]);
    }
}

__global__ __launch_bounds__(256)
void convert_wt4(const float* __restrict__ W0, const float* __restrict__ W1,
                 const float* __restrict__ W2, const float* __restrict__ W3,
                 __half* __restrict__ O0, __half* __restrict__ O1,
                 __half* __restrict__ O2, __half* __restrict__ O3)
{
    int gid = blockIdx.x * 256 + threadIdx.x;
    int which = gid >> 18;
    int idx = gid & ((1 << 18) - 1);
    int n = idx >> 9, k = idx & 511;
    const float* W = (which == 0) ? W0 : (which == 1) ? W1 : (which == 2) ? W2 : W3;
    __half* O = (which == 0) ? O0 : (which == 1) ? O1 : (which == 2) ? O2 : O3;
    O[(size_t)n * HID + k] = __float2half_rn(W[(size_t)k * HID + n]);
}

__global__ void bias_cat(const float* bq, const float* bk, const float* bv, float* o)
{
    int i = blockIdx.x * 256 + threadIdx.x;
    if (i < HID) { o[i] = bq[i]; o[HID + i] = bk[i]; o[2 * HID + i] = bv[i]; }
}

// =====================================================================
// fp16 mma.sync GEMM (R8 config): BM=BN=128, BK=64; 4 warps (2x2),
// 64x64 warp tile; 128 threads, 2 CTAs/SM, 3-stage cp.async (32KB/stage).
// MODE 2: fp32 out = acc + bias + res
// MODE 3: QKV: fp16 out to head layout with per-col alpha (Q only)
// MODE 4: relu, fp16 out (FFN1)
// =====================================================================
template<int MODE>
__global__ __launch_bounds__(128, 2)
void mm_gemm(const __half* __restrict__ A, const __half* __restrict__ Bt,
             const float* __restrict__ bias, const float* __restrict__ res,
             float* __restrict__ C, __half* __restrict__ Ch,
             int N, int Kstride, int Kiter, float alpha)
{
    extern __shared__ char smc[];
    const uint32_t sb = smem_u32(smc);
    const int tid = threadIdx.x, lane = tid & 31, w = tid >> 5;
    const int wm = w >> 1, wn = w & 1;
    const int bm = blockIdx.y * 128, bn = blockIdx.x * 128;
    const int nt = Kiter / 64;
    const __half* Ag = A + (size_t)bm * Kstride;
    const __half* Bg = Bt + (size_t)bn * Kstride;

    auto load_tile = [&](int t) {
        const int st = t % 3;
        const uint32_t sa = sb + st * 32768, sbb = sa + 16384;
        const __half* Ap = Ag + t * 64;
        const __half* Bp = Bg + t * 64;
        #pragma unroll
        for (int i = 0; i < 8; i++) {
            int idx = tid + i * 128;
            int r = idx >> 3, q = idx & 7;
            uint32_t so = off128(r, q);
            CP16(sa + so, Ap + (size_t)r * Kstride + q * 8);
            CP16(sbb + so, Bp + (size_t)r * Kstride + q * 8);
        }
        CP_COMMIT();
    };
    load_tile(0); load_tile(1);

    float acc[4][8][4];
    #pragma unroll
    for (int a0 = 0; a0 < 4; a0++)
        #pragma unroll
        for (int b0 = 0; b0 < 8; b0++)
            #pragma unroll
            for (int c0 = 0; c0 < 4; c0++) acc[a0][b0][c0] = 0.f;

    for (int t = 0; t < nt; t++) {
        CP_WAIT(1);
        __syncthreads();
        if (t + 2 < nt) load_tile(t + 2);
        const int st = t % 3;
        const uint32_t sa = sb + st * 32768, sbb = sa + 16384;
        #pragma unroll
        for (int j = 0; j < 4; j++) {
            uint32_t af[4][4], bf[4][4];
            const int q = j * 2 + (lane >> 4);
            #pragma unroll
            for (int mi = 0; mi < 4; mi++) {
                int r = wm * 64 + mi * 16 + (lane & 15);
                ldm_x4(af[mi], sa + off128(r, q));
            }
            #pragma unroll
            for (int ni = 0; ni < 4; ni++) {
                int r = wn * 64 + ni * 16 + (lane & 15);
                ldm_x4(bf[ni], sbb + off128(r, q));
            }
            #pragma unroll
            for (int mi = 0; mi < 4; mi++)
                #pragma unroll
                for (int nj = 0; nj < 8; nj++)
                    mma_f16(acc[mi][nj], af[mi],
                            bf[nj >> 1][nj & 1], bf[nj >> 1][2 + (nj & 1)]);
        }
    }

    // epilogue
    #pragma unroll
    for (int mi = 0; mi < 4; mi++) {
        #pragma unroll
        for (int hh = 0; hh < 2; hh++) {
            const int row = bm + wm * 64 + mi * 16 + hh * 8 + (lane >> 2);
            #pragma unroll
            for (int nj = 0; nj < 8; nj++) {
                const int col = bn + wn * 64 + nj * 8 + 2 * (lane & 3);
                float v0 = acc[mi][nj][2 * hh]     + bias[col];
                float v1 = acc[mi][nj][2 * hh + 1] + bias[col + 1];
                if (MODE == 2) {
                    float2 rr = *(const float2*)(res + (size_t)row * N + col);
                    float2 vv; vv.x = v0 + rr.x; vv.y = v1 + rr.y;
                    *(float2*)(C + (size_t)row * N + col) = vv;
                }
                if (MODE == 3) {
                    float sc = (col < HID) ? alpha : 1.f;
                    int t = col >> 9, rem = col & 511;
                    int b = row >> 11, s = row & 2047, hd = rem >> 6, d = rem & 63;
                    __half2 p;
                    p.x = __float2half_rn(v0 * sc);
                    p.y = __float2half_rn(v1 * sc);
                    *(__half2*)(g_QKVh + (size_t)t * BHSD +
                        ((((size_t)b * NHEAD + hd) * SEQ + s) * DHEAD + d)) = p;
                }
                if (MODE == 4) {
                    __half2 p;
                    p.x = __float2half_rn(fmaxf(v0, 0.f));
                    p.y = __float2half_rn(fmaxf(v1, 0.f));
                    *(__half2*)(Ch + (size_t)row * N + col) = p;
                }
            }
        }
    }
}

// =====================================================================
// FA2-style fp16 attention, no online max, exp2 softmax.
// 256 q/CTA, 8 warps (32 q-rows each). 4-stage KV ring, 2 chunks per
// loop body. smem: Q 32KB + 4 x (K 8KB + V 8KB) = 96KB.
// =====================================================================
__global__ __launch_bounds__(256)
void attn_mma(__half* __restrict__ AoutH)
{
    extern __shared__ char smc[];
    const uint32_t sb = smem_u32(smc);
    const int tid = threadIdx.x, lane = tid & 31, w = tid >> 5;
    const int bh = blockIdx.y, qbase = blockIdx.x * 256;
    const int b = bh >> 3, h = bh & 7;
    const __half* Qp = g_QKVh + ((size_t)bh * SEQ + qbase) * DHEAD;
    const __half* Kp = g_QKVh + BHSD + (size_t)bh * SEQ * DHEAD;
    const __half* Vp = g_QKVh + 2 * BHSD + (size_t)bh * SEQ * DHEAD;

    // Q tile: 256 rows x 128B (swizzled)
    #pragma unroll
    for (int i = 0; i < 8; i++) {
        int idx = tid + i * 256;
        int r = idx >> 3, q = idx & 7;
        *(uint4*)(smc + off128(r, q)) = *(const uint4*)(Qp + (size_t)r * DHEAD + q * 8);
    }
    __syncthreads();

    uint32_t qf[2][4][4];
    #pragma unroll
    for (int mi = 0; mi < 2; mi++)
        #pragma unroll
        for (int dk = 0; dk < 4; dk++) {
            int r = w * 32 + mi * 16 + (lane & 15);
            int q = dk * 2 + (lane >> 4);
            ldm_x4(qf[mi][dk], sb + off128(r, q));
        }

    float o[2][8][4];
    #pragma unroll
    for (int mi = 0; mi < 2; mi++)
        #pragma unroll
        for (int dj = 0; dj < 8; dj++)
            #pragma unroll
            for (int c0 = 0; c0 < 4; c0++) o[mi][dj][c0] = 0.f;
    float lrun[2][2] = {{0.f, 0.f}, {0.f, 0.f}};

    auto load_kv = [&](int c) {
        const int st = c & 3;
        const uint32_t sk = sb + 32768 + st * 16384;
        const uint32_t sv = sk + 8192;
        const __half* Kc = Kp + (size_t)c * 64 * DHEAD;
        const __half* Vc = Vp + (size_t)c * 64 * DHEAD;
        #pragma unroll
        for (int i = 0; i < 2; i++) {
            int idx = tid + i * 256;
            int r = idx >> 3, q = idx & 7;
            uint32_t so = off128(r, q);
            CP16(sk + so, Kc + (size_t)r * DHEAD + q * 8);
            CP16(sv + so, Vc + (size_t)r * DHEAD + q * 8);
        }
        CP_COMMIT();
    };

    auto compute_chunk = [&](int c) {
        const int st = c & 3;
        const uint32_t sk = sb + 32768 + st * 16384;
        const uint32_t sv = sk + 8192;

        float s[2][8][4];
        #pragma unroll
        for (int mi = 0; mi < 2; mi++)
            #pragma unroll
            for (int nj = 0; nj < 8; nj++)
                #pragma unroll
                for (int c0 = 0; c0 < 4; c0++) s[mi][nj][c0] = 0.f;

        #pragma unroll
        for (int dk = 0; dk < 4; dk++) {
            uint32_t kf[4][4];
            const int q = dk * 2 + (lane >> 4);
            #pragma unroll
            for (int bq = 0; bq < 4; bq++) {
                int r = bq * 16 + (lane & 15);
                ldm_x4(kf[bq], sk + off128(r, q));
            }
            #pragma unroll
            for (int mi = 0; mi < 2; mi++)
                #pragma unroll
                for (int nj = 0; nj < 8; nj++)
                    mma_f16(s[mi][nj], qf[mi][dk],
                            kf[nj >> 1][nj & 1], kf[nj >> 1][2 + (nj & 1)]);
        }

        // P = 2^S (log2e folded into Q scale)
        #pragma unroll
        for (int mi = 0; mi < 2; mi++)
            #pragma unroll
            for (int hh = 0; hh < 2; hh++) {
                float sum = 0.f;
                #pragma unroll
                for (int nj = 0; nj < 8; nj++) {
                    float e0 = ex2f(s[mi][nj][2 * hh]);
                    float e1 = ex2f(s[mi][nj][2 * hh + 1]);
                    s[mi][nj][2 * hh] = e0;
                    s[mi][nj][2 * hh + 1] = e1;
                    sum += e0 + e1;
                }
                lrun[mi][hh] += sum;
            }

        uint32_t pf[2][4][4];
        #pragma unroll
        for (int mi = 0; mi < 2; mi++)
            #pragma unroll
            for (int ki = 0; ki < 4; ki++) {
                pf[mi][ki][0] = pack_h(s[mi][2 * ki][0],     s[mi][2 * ki][1]);
                pf[mi][ki][1] = pack_h(s[mi][2 * ki][2],     s[mi][2 * ki][3]);
                pf[mi][ki][2] = pack_h(s[mi][2 * ki + 1][0], s[mi][2 * ki + 1][1]);
                pf[mi][ki][3] = pack_h(s[mi][2 * ki + 1][2], s[mi][2 * ki + 1][3]);
            }

        #pragma unroll
        for (int ki = 0; ki < 4; ki++) {
            uint32_t vf[4][4];
            #pragma unroll
            for (int db = 0; db < 4; db++) {
                int r = ki * 16 + (lane & 15);
                int q = db * 2 + (lane >> 4);
                ldm_x4_t(vf[db], sv + off128(r, q));
            }
            #pragma unroll
            for (int mi = 0; mi < 2; mi++)
                #pragma unroll
                for (int dj = 0; dj < 8; dj++)
                    mma_f16(o[mi][dj], pf[mi][ki],
                            vf[dj >> 1][(dj & 1) * 2], vf[dj >> 1][(dj & 1) * 2 + 1]);
        }
    };

    load_kv(0); load_kv(1); load_kv(2); load_kv(3);

    const int NC = SEQ / 64;
    for (int c = 0; c < NC; c += 2) {
        CP_WAIT(2);
        __syncthreads();
        compute_chunk(c);
        compute_chunk(c + 1);
        __syncthreads();
        if (c + 4 < NC) load_kv(c + 4);
        if (c + 5 < NC) load_kv(c + 5);
    }

    #pragma unroll
    for (int mi = 0; mi < 2; mi++)
        #pragma unroll
        for (int hh = 0; hh < 2; hh++) {
            lrun[mi][hh] += __shfl_xor_sync(0xffffffffu, lrun[mi][hh], 1);
            lrun[mi][hh] += __shfl_xor_sync(0xffffffffu, lrun[mi][hh], 2);
        }

    #pragma unroll
    for (int mi = 0; mi < 2; mi++)
        #pragma unroll
        for (int hh = 0; hh < 2; hh++) {
            const int srow = qbase + w * 32 + mi * 16 + hh * 8 + (lane >> 2);
            const float inv = 1.f / lrun[mi][hh];
            #pragma unroll
            for (int dj = 0; dj < 8; dj++) {
                const int col = h * 64 + dj * 8 + 2 * (lane & 3);
                __half2 p;
                p.x = __float2half_rn(o[mi][dj][2 * hh] * inv);
                p.y = __float2half_rn(o[mi][dj][2 * hh + 1] * inv);
                *(__half2*)(AoutH + ((size_t)b * SEQ + srow) * HID + col) = p;
            }
        }
}

// =====================================================================
// LayerNorm. HOUT=1 also writes plain fp16 row (FFN1 input).
// =====================================================================
template<int HOUT>
__global__ __launch_bounds__(128)
void layernorm_kernel(const float* __restrict__ X, const float* __restrict__ g,
                      const float* __restrict__ b, float* __restrict__ Y,
                      __half* __restrict__ Yh)
{
    const int row = blockIdx.x;
    const int tid = threadIdx.x;
    const float4 v = ((const float4*)(X + (size_t)row * HID))[tid];

    float s  = v.x + v.y + v.z + v.w;
    float ss = v.x*v.x + v.y*v.y + v.z*v.z + v.w*v.w;
    #pragma unroll
    for (int o = 16; o > 0; o >>= 1) {
        s  += __shfl_xor_sync(0xffffffffu, s,  o);
        ss += __shfl_xor_sync(0xffffffffu, ss, o);
    }
    __shared__ float sh[8];
    const int wid = tid >> 5, lane = tid & 31;
    if (lane == 0) { sh[wid] = s; sh[4 + wid] = ss; }
    __syncthreads();
    s  = sh[0] + sh[1] + sh[2] + sh[3];
    ss = sh[4] + sh[5] + sh[6] + sh[7];

    const float mean = s * (1.f / HID);
    const float var  = ss * (1.f / HID) - mean * mean;
    const float rstd = rsqrtf(var + 1e-5f);

    const float4 gg = ((const float4*)g)[tid];
    const float4 bb = ((const float4*)b)[tid];
    float4 out;
    out.x = (v.x - mean) * rstd * gg.x + bb.x;
    out.y = (v.y - mean) * rstd * gg.y + bb.y;
    out.z = (v.z - mean) * rstd * gg.z + bb.z;
    out.w = (v.w - mean) * rstd * gg.w + bb.w;
    ((float4*)(Y + (size_t)row * HID))[tid] = out;

    if (HOUT) {
        __half2 a, c;
        a.x = __float2half_rn(out.x); a.y = __float2half_rn(out.y);
        c.x = __float2half_rn(out.z); c.y = __float2half_rn(out.w);
        *(__half2*)(Yh + (size_t)row * HID + tid * 4) = a;
        *(__half2*)(Yh + (size_t)row * HID + tid * 4 + 2) = c;
    }
}

// =====================================================================
// Launch (QKV GEMM is the 5th launch -> captured by ncu -s 5 -c 1)
// =====================================================================
extern "C" void kernel_launch(void* const* d_in, const int* in_sizes, int n_in,
                              void* d_out, int out_size)
{
    const float* X   = (const float*)d_in[0];
    const float* Wq  = (const float*)d_in[2];
    const float* bq  = (const float*)d_in[3];
    const float* Wk  = (const float*)d_in[4];
    const float* bk  = (const float*)d_in[5];
    const float* Wv  = (const float*)d_in[6];
    const float* bv  = (const float*)d_in[7];
    const float* Wo  = (const float*)d_in[8];
    const float* bo  = (const float*)d_in[9];
    const float* g1  = (const float*)d_in[10];
    const float* b1  = (const float*)d_in[11];
    const float* W1  = (const float*)d_in[12];
    const float* bf1 = (const float*)d_in[13];
    const float* W2  = (const float*)d_in[14];
    const float* bf2 = (const float*)d_in[15];
    const float* g2  = (const float*)d_in[16];
    const float* b2  = (const float*)d_in[17];
    float* out = (float*)d_out;

    void *pQKV,*pAtt,*pR,*pL1,*pXh,*pL1h,*pF2,*pWqkv,*pWoh,*pW1h,*pW2h,*pBqkv;
    cudaGetSymbolAddress(&pQKV, g_QKVh); cudaGetSymbolAddress(&pAtt, g_AttnH);
    cudaGetSymbolAddress(&pR, g_R);      cudaGetSymbolAddress(&pL1, g_L1);
    cudaGetSymbolAddress(&pXh, g_Xh);    cudaGetSymbolAddress(&pL1h, g_L1h);
    cudaGetSymbolAddress(&pF2, g_F2);    cudaGetSymbolAddress(&pWqkv, g_Wqkv);
    cudaGetSymbolAddress(&pWoh, g_Woh);  cudaGetSymbolAddress(&pW1h, g_W1h);
    cudaGetSymbolAddress(&pW2h, g_W2h);  cudaGetSymbolAddress(&pBqkv, g_bqkv);

    const int GEMM_SMEM = 98304;     // 3 stages x 32KB
    cudaFuncSetAttribute(mm_gemm<2>, cudaFuncAttributeMaxDynamicSharedMemorySize, GEMM_SMEM);
    cudaFuncSetAttribute(mm_gemm<3>, cudaFuncAttributeMaxDynamicSharedMemorySize, GEMM_SMEM);
    cudaFuncSetAttribute(mm_gemm<4>, cudaFuncAttributeMaxDynamicSharedMemorySize, GEMM_SMEM);
    const int ATT_SMEM = 98304;      // Q 32KB + 4 x 16KB KV
    cudaFuncSetAttribute(attn_mma, cudaFuncAttributeMaxDynamicSharedMemorySize, ATT_SMEM);

    // log2(e)/sqrt(dh): folds attention scale and exp->exp2 base change into Q
    const float qscale = 1.44269504088896340736f / sqrtf((float)DHEAD);

    // launches 1-4 (1-based): conversions; launch 5 = QKV GEMM
    bias_cat<<<2, 256>>>(bq, bk, bv, (float*)pBqkv);                                   // 1
    convert_x<<<(MROWS*HID + 255)/256, 256>>>(X, (__half*)pXh, MROWS*HID);             // 2
    convert_wt4<<<(4*HID*HID)/256, 256>>>(Wq, Wk, Wv, Wo,                              // 3
        (__half*)pWqkv, (__half*)pWqkv + (size_t)HID*HID,
        (__half*)pWqkv + (size_t)2*HID*HID, (__half*)pWoh);
    convert_w12<<<(2*HID*FFN)/256, 256>>>(W1, W2, (__half*)pW1h, (__half*)pW2h);       // 4

    // 5: fused QKV projection -> fp16 head layout
    mm_gemm<3><<<dim3(3*HID/128, MROWS/128), 128, GEMM_SMEM>>>(
        (__half*)pXh, (__half*)pWqkv, (float*)pBqkv, nullptr, nullptr, nullptr,
        3*HID, HID, HID, qscale);

    // 6: attention (256 q-rows per CTA)
    attn_mma<<<dim3(SEQ/256, BATCH*NHEAD), 256, ATT_SMEM>>>((__half*)pAtt);

    // 7-8: Wo + residual, LN1 (+fp16 out)
    mm_gemm<2><<<dim3(HID/128, MROWS/128), 128, GEMM_SMEM>>>(
        (__half*)pAtt, (__half*)pWoh, bo, X, (float*)pR, nullptr, HID, HID, HID, 1.f);
    layernorm_kernel<1><<<MROWS, 128>>>((float*)pR, g1, b1, (float*)pL1, (__half*)pL1h);

    // 9: FFN1: plain fp16, relu
    mm_gemm<4><<<dim3(FFN/128, MROWS/128), 128, GEMM_SMEM>>>(
        (__half*)pL1h, (__half*)pW1h, bf1, nullptr, nullptr, (__half*)pF2,
        FFN, HID, HID, 1.f);

    // 10: FFN2: plain fp16 + residual
    mm_gemm<2><<<dim3(HID/128, MROWS/128), 128, GEMM_SMEM>>>(
        (__half*)pF2, (__half*)pW2h, bf2, (float*)pL1, (float*)pR, nullptr,
        HID, FFN, FFN, 1.f);

    // 11: LN2 -> out
    layernorm_kernel<0><<<MROWS, 128>>>((float*)pR, g2, b2, out, nullptr);
}